// round 11
// baseline (speedup 1.0000x reference)
#include <cuda_runtime.h>
#include <math.h>

#define NUM_B 8192
#define T_LEN 1024
#define HID   64
#define EPSF  1e-6f
#define SEGS  32
#define SLEN  (T_LEN / SEGS)
#define OPITCH 36
#define HPITCH 68
#define MROWS 64
#define BWARPS 8

// Per-row scan constants (odds-space affine recurrence).
__device__ float g_A0[NUM_B], g_A1[NUM_B], g_B[NUM_B],
                 g_o0[NUM_B], g_s1[NUM_B], g_gg[NUM_B];

// ---------------------------------------------------------------------------
// Kernel 1: MLP (identical to R10 passing version).
// ---------------------------------------------------------------------------
__global__ __launch_bounds__(256) void mlp_kernel(
    const int*   __restrict__ X,
    const float* __restrict__ embed,
    const float* __restrict__ W0, const float* __restrict__ b0,
    const float* __restrict__ W1, const float* __restrict__ b1,
    const float* __restrict__ Wout, const float* __restrict__ bout)
{
    __shared__ float sW[HID * HID];
    __shared__ float sWo[HID * 4];
    __shared__ float sb0[HID], sb1[HID], sbo[4];
    __shared__ float sh[MROWS][HPITCH];
    __shared__ float sp[MROWS][4];

    const int t = threadIdx.x;

#pragma unroll
    for (int i = t; i < HID * HID / 4; i += 256)
        reinterpret_cast<float4*>(sW)[i] = reinterpret_cast<const float4*>(W0)[i];
    if (t < HID) { sb0[t] = b0[t]; sb1[t] = b1[t]; }
    if (t < HID) reinterpret_cast<float4*>(sWo)[t] = reinterpret_cast<const float4*>(Wout)[t];
    if (t < 4)   sbo[t] = bout[t];

    const int c4 = (t & 7) * 4;
    const int rp = (t >> 3) * 2;
    const int growbase = blockIdx.x * MROWS;

#pragma unroll
    for (int rr = 0; rr < 2; ++rr) {
        const int xi = X[growbase + rp + rr];
        const float4 e0 = *reinterpret_cast<const float4*>(&embed[(size_t)xi * HID + c4]);
        const float4 e1 = *reinterpret_cast<const float4*>(&embed[(size_t)xi * HID + c4 + 32]);
        *reinterpret_cast<float4*>(&sh[rp + rr][c4])      = e0;
        *reinterpret_cast<float4*>(&sh[rp + rr][c4 + 32]) = e1;
    }
    __syncthreads();

    float acc[16];

    // layer 0
#pragma unroll
    for (int rr = 0; rr < 2; ++rr)
#pragma unroll
        for (int k = 0; k < 4; ++k) {
            acc[rr * 8 + k]     = sb0[c4 + k];
            acc[rr * 8 + 4 + k] = sb0[c4 + 32 + k];
        }
#pragma unroll
    for (int i = 0; i < HID; ++i) {
        const float4 w0 = *reinterpret_cast<const float4*>(&sW[i * HID + c4]);
        const float4 w1 = *reinterpret_cast<const float4*>(&sW[i * HID + c4 + 32]);
#pragma unroll
        for (int rr = 0; rr < 2; ++rr) {
            const float hb = sh[rp + rr][i];
            acc[rr*8+0] = fmaf(hb, w0.x, acc[rr*8+0]);
            acc[rr*8+1] = fmaf(hb, w0.y, acc[rr*8+1]);
            acc[rr*8+2] = fmaf(hb, w0.z, acc[rr*8+2]);
            acc[rr*8+3] = fmaf(hb, w0.w, acc[rr*8+3]);
            acc[rr*8+4] = fmaf(hb, w1.x, acc[rr*8+4]);
            acc[rr*8+5] = fmaf(hb, w1.y, acc[rr*8+5]);
            acc[rr*8+6] = fmaf(hb, w1.z, acc[rr*8+6]);
            acc[rr*8+7] = fmaf(hb, w1.w, acc[rr*8+7]);
        }
    }
    __syncthreads();

#pragma unroll
    for (int rr = 0; rr < 2; ++rr) {
        float4 h0, h1;
        h0.x = fmaxf(acc[rr*8+0], 0.0f); h0.y = fmaxf(acc[rr*8+1], 0.0f);
        h0.z = fmaxf(acc[rr*8+2], 0.0f); h0.w = fmaxf(acc[rr*8+3], 0.0f);
        h1.x = fmaxf(acc[rr*8+4], 0.0f); h1.y = fmaxf(acc[rr*8+5], 0.0f);
        h1.z = fmaxf(acc[rr*8+6], 0.0f); h1.w = fmaxf(acc[rr*8+7], 0.0f);
        *reinterpret_cast<float4*>(&sh[rp + rr][c4])      = h0;
        *reinterpret_cast<float4*>(&sh[rp + rr][c4 + 32]) = h1;
    }
#pragma unroll
    for (int i = t; i < HID * HID / 4; i += 256)
        reinterpret_cast<float4*>(sW)[i] = reinterpret_cast<const float4*>(W1)[i];
    __syncthreads();

    // layer 1
#pragma unroll
    for (int rr = 0; rr < 2; ++rr)
#pragma unroll
        for (int k = 0; k < 4; ++k) {
            acc[rr * 8 + k]     = sb1[c4 + k];
            acc[rr * 8 + 4 + k] = sb1[c4 + 32 + k];
        }
#pragma unroll
    for (int i = 0; i < HID; ++i) {
        const float4 w0 = *reinterpret_cast<const float4*>(&sW[i * HID + c4]);
        const float4 w1 = *reinterpret_cast<const float4*>(&sW[i * HID + c4 + 32]);
#pragma unroll
        for (int rr = 0; rr < 2; ++rr) {
            const float hb = sh[rp + rr][i];
            acc[rr*8+0] = fmaf(hb, w0.x, acc[rr*8+0]);
            acc[rr*8+1] = fmaf(hb, w0.y, acc[rr*8+1]);
            acc[rr*8+2] = fmaf(hb, w0.z, acc[rr*8+2]);
            acc[rr*8+3] = fmaf(hb, w0.w, acc[rr*8+3]);
            acc[rr*8+4] = fmaf(hb, w1.x, acc[rr*8+4]);
            acc[rr*8+5] = fmaf(hb, w1.y, acc[rr*8+5]);
            acc[rr*8+6] = fmaf(hb, w1.z, acc[rr*8+6]);
            acc[rr*8+7] = fmaf(hb, w1.w, acc[rr*8+7]);
        }
    }
    __syncthreads();
#pragma unroll
    for (int rr = 0; rr < 2; ++rr) {
        float4 h0, h1;
        h0.x = fmaxf(acc[rr*8+0], 0.0f); h0.y = fmaxf(acc[rr*8+1], 0.0f);
        h0.z = fmaxf(acc[rr*8+2], 0.0f); h0.w = fmaxf(acc[rr*8+3], 0.0f);
        h1.x = fmaxf(acc[rr*8+4], 0.0f); h1.y = fmaxf(acc[rr*8+5], 0.0f);
        h1.z = fmaxf(acc[rr*8+6], 0.0f); h1.w = fmaxf(acc[rr*8+7], 0.0f);
        *reinterpret_cast<float4*>(&sh[rp + rr][c4])      = h0;
        *reinterpret_cast<float4*>(&sh[rp + rr][c4 + 32]) = h1;
    }
    __syncthreads();

    {
        const int hr = t >> 2;
        const int jo = t & 3;
        float a2 = sbo[jo];
#pragma unroll
        for (int i = 0; i < HID; ++i) a2 = fmaf(sh[hr][i], sWo[i * 4 + jo], a2);
        float pv = 1.0f / (1.0f + expf(-a2));
        sp[hr][jo] = fminf(fmaxf(pv, EPSF), 1.0f - EPSF);
    }
    __syncthreads();

    if (t < MROWS) {
        const int rr   = growbase + t;
        const float l  = sp[t][0];
        const float gg = sp[t][1];
        const float s  = sp[t][2];
        const float pr = sp[t][3];
        const float il = 1.0f / (1.0f - l);
        g_A1[rr] = (1.0f - s) / (gg * (1.0f - l));
        g_A0[rr] = s / ((1.0f - gg) * (1.0f - l));
        g_B[rr]  = l * il;
        g_o0[rr] = pr / (1.0f - pr);
        g_s1[rr] = 1.0f - s;
        g_gg[rr] = gg;
    }
}

// ---------------------------------------------------------------------------
// Kernel 2: warp-per-row BKT scan.
// R11 deltas: launch_bounds(256,6) (reg clamp -> 6 blocks/SM), y preload in
// 8-entry batches (lower peak regs), drain uses correct = fmaf(latent, aC, g).
// ---------------------------------------------------------------------------
__global__ __launch_bounds__(256, 6) void bkt_kernel(
    const int* __restrict__ y, float* __restrict__ out)
{
    __shared__ __align__(16) float s_o[BWARPS][SEGS * OPITCH];

    const int w    = threadIdx.x >> 5;
    const int lane = threadIdx.x & 31;
    const int row  = blockIdx.x * BWARPS + w;

    const float A0 = g_A0[row];
    const float A1 = g_A1[row];
    const float Bc = g_B[row];
    const float gg = g_gg[row];
    const float aC = g_s1[row] - gg;      // 1 - s - g
    const float o0 = g_o0[row];
    const float OMAX = (1.0f - EPSF) / EPSF;

    // 1) mask build: 4 batches of (8 preloads -> 8 ballots)
    const int* yrow = y + (size_t)row * T_LEN;
    unsigned mask = 0;
#pragma unroll
    for (int h = 0; h < 4; ++h) {
        int v[8];
#pragma unroll
        for (int c = 0; c < 8; ++c) v[c] = yrow[(h * 8 + c) * SLEN + lane];
#pragma unroll
        for (int c = 0; c < 8; ++c) {
            const unsigned m = __ballot_sync(0xffffffffu, v[c] > 0);
            if (lane == h * 8 + c) mask = m;
        }
    }

    // 2) compose segment map f(o) = min(a*o + b, c)
    float a = 1.0f, b = 0.0f, cc = OMAX;
#pragma unroll
    for (int j = 0; j < SLEN; ++j) {
        const float A = ((mask >> j) & 1u) ? A1 : A0;
        cc = fminf(fmaf(A, cc, Bc), OMAX);
        b  = fmaf(A, b, Bc);
        a  = A * a;
    }

    // 3) inclusive Kogge-Stone scan over maps
#pragma unroll
    for (int d = 1; d < 32; d <<= 1) {
        const float ap = __shfl_up_sync(0xffffffffu, a,  d);
        const float bp = __shfl_up_sync(0xffffffffu, b,  d);
        const float cp = __shfl_up_sync(0xffffffffu, cc, d);
        if (lane >= d) {
            const float bn = fmaf(a, bp, b);
            const float cn = fminf(fmaf(a, cp, b), cc);
            a  = a * ap;
            b  = bn;
            cc = cn;
        }
    }
    const float ap = __shfl_up_sync(0xffffffffu, a,  1);
    const float bp = __shfl_up_sync(0xffffffffu, b,  1);
    const float cp = __shfl_up_sync(0xffffffffu, cc, 1);
    float o = (lane == 0) ? o0 : fminf(fmaf(ap, o0, bp), cp);

    // 4) emit: batch 4 steps into float4, STS.128
    float* const so = &s_o[w][lane * OPITCH];
#pragma unroll
    for (int j4 = 0; j4 < SLEN / 4; ++j4) {
        float4 ov;
        {   const float A = ((mask >> (4*j4+0)) & 1u) ? A1 : A0;
            ov.x = o;  o = fminf(fmaf(A, o, Bc), OMAX); }
        {   const float A = ((mask >> (4*j4+1)) & 1u) ? A1 : A0;
            ov.y = o;  o = fminf(fmaf(A, o, Bc), OMAX); }
        {   const float A = ((mask >> (4*j4+2)) & 1u) ? A1 : A0;
            ov.z = o;  o = fminf(fmaf(A, o, Bc), OMAX); }
        {   const float A = ((mask >> (4*j4+3)) & 1u) ? A1 : A0;
            ov.w = o;  o = fminf(fmaf(A, o, Bc), OMAX); }
        *reinterpret_cast<float4*>(so + 4 * j4) = ov;
    }
    __syncwarp();

    // 5) drain: latent = o*rcp(1+o); correct = fmaf(latent, aC, gg)
    float* const outc = out + (size_t)row * T_LEN;
    float* const outl = out + (size_t)NUM_B * T_LEN + (size_t)row * T_LEN;
    const int sgl = lane >> 3;
    const int k4  = (lane & 7) * 4;
#pragma unroll
    for (int dd = 0; dd < 8; ++dd) {
        const int seg = dd * 4 + sgl;
        const float4 ov = *reinterpret_cast<const float4*>(&s_o[w][seg * OPITCH + k4]);
        float4 lv, cv;
        float inv;
        asm("rcp.approx.ftz.f32 %0, %1;" : "=f"(inv) : "f"(1.0f + ov.x));
        lv.x = ov.x * inv;  cv.x = fmaf(lv.x, aC, gg);
        asm("rcp.approx.ftz.f32 %0, %1;" : "=f"(inv) : "f"(1.0f + ov.y));
        lv.y = ov.y * inv;  cv.y = fmaf(lv.y, aC, gg);
        asm("rcp.approx.ftz.f32 %0, %1;" : "=f"(inv) : "f"(1.0f + ov.z));
        lv.z = ov.z * inv;  cv.z = fmaf(lv.z, aC, gg);
        asm("rcp.approx.ftz.f32 %0, %1;" : "=f"(inv) : "f"(1.0f + ov.w));
        lv.w = ov.w * inv;  cv.w = fmaf(lv.w, aC, gg);
        *reinterpret_cast<float4*>(outc + seg * SLEN + k4) = cv;
        *reinterpret_cast<float4*>(outl + seg * SLEN + k4) = lv;
    }
}

// ---------------------------------------------------------------------------
extern "C" void kernel_launch(void* const* d_in, const int* in_sizes, int n_in,
                              void* d_out, int out_size)
{
    const int*   X     = (const int*)  d_in[0];
    const int*   y     = (const int*)  d_in[1];
    const float* embed = (const float*)d_in[2];
    const float* W0    = (const float*)d_in[3];
    const float* b0    = (const float*)d_in[4];
    const float* W1    = (const float*)d_in[5];
    const float* b1    = (const float*)d_in[6];
    const float* Wout  = (const float*)d_in[7];
    const float* bout  = (const float*)d_in[8];

    mlp_kernel<<<NUM_B / MROWS, 256>>>(X, embed, W0, b0, W1, b1, Wout, bout);
    bkt_kernel<<<NUM_B / BWARPS, 32 * BWARPS>>>(y, (float*)d_out);
}

// round 12
// speedup vs baseline: 1.0077x; 1.0077x over previous
#include <cuda_runtime.h>
#include <math.h>

#define NUM_B 8192
#define T_LEN 1024
#define HID   64
#define EPSF  1e-6f
#define SEGS  32
#define SLEN  (T_LEN / SEGS)
#define OPITCH 36
#define BWARPS 8

// ---------------------------------------------------------------------------
// Fused kernel: per-block (8 rows) MLP -> odds-space constants -> warp-per-row
// BKT scan. 1024 blocks x 256 threads. The W staging buffer aliases the scan's
// output staging array (phases are sync-separated).
// ---------------------------------------------------------------------------
__global__ __launch_bounds__(256) void fused_kernel(
    const int*   __restrict__ X,
    const int*   __restrict__ y,
    const float* __restrict__ embed,
    const float* __restrict__ W0, const float* __restrict__ b0,
    const float* __restrict__ W1, const float* __restrict__ b1,
    const float* __restrict__ Wout, const float* __restrict__ bout,
    float*       __restrict__ out)
{
    __shared__ __align__(16) float s_o[BWARPS][SEGS * OPITCH];  // 36.9 KB (also W buffer)
    __shared__ float sh[2][BWARPS][66];
    __shared__ float sWo[HID * 4];
    __shared__ float sb0[HID], sb1[HID], sbo[4];
    __shared__ float sp[BWARPS][4];
    __shared__ float cA0[BWARPS], cA1[BWARPS], cB[BWARPS],
                     cO0[BWARPS], cS1[BWARPS], cGG[BWARPS];
    __shared__ int   sX[BWARPS];

    float* const sW = &s_o[0][0];           // 4096 floats = 16 KB alias

    const int t    = threadIdx.x;
    const int w    = t >> 5;
    const int lane = t & 31;
    const int rowbase = blockIdx.x * BWARPS;
    const int row  = rowbase + w;
    const int c2   = lane * 2;

    // ---- stage W0 + small tensors (stores drain at the next syncthreads) ----
#pragma unroll
    for (int i = t; i < HID * HID / 4; i += 256)
        reinterpret_cast<float4*>(sW)[i] = reinterpret_cast<const float4*>(W0)[i];
    if (t < HID) {
        sb0[t] = b0[t];  sb1[t] = b1[t];
        reinterpret_cast<float4*>(sWo)[t] = reinterpret_cast<const float4*>(Wout)[t];
    }
    if (t < 4)      sbo[t] = bout[t];
    if (t < BWARPS) sX[t]  = X[rowbase + t];

    // ---- mask build (independent of MLP; overlaps staging latency) ----
    const int* yrow = y + (size_t)row * T_LEN;
    unsigned mask = 0;
    {
        int v[16];
#pragma unroll
        for (int c = 0; c < 16; ++c) v[c] = yrow[c * SLEN + lane];
#pragma unroll
        for (int c = 0; c < 16; ++c) {
            const unsigned m = __ballot_sync(0xffffffffu, v[c] > 0);
            if (lane == c) mask = m;
        }
#pragma unroll
        for (int c = 0; c < 16; ++c) v[c] = yrow[(16 + c) * SLEN + lane];
#pragma unroll
        for (int c = 0; c < 16; ++c) {
            const unsigned m = __ballot_sync(0xffffffffu, v[c] > 0);
            if (lane == 16 + c) mask = m;
        }
    }
    __syncthreads();   // W0, biases, sX visible

    // ---- embed gather: warp w = row w (warp-local) ----
    {
        const int xi = sX[w];
        const float2 e = *reinterpret_cast<const float2*>(&embed[(size_t)xi * HID + c2]);
        sh[0][w][c2]     = e.x;
        sh[0][w][c2 + 1] = e.y;
    }
    __syncwarp();

    // ---- layer 0: lane owns cols c2, c2+1 of row w ----
    float a0 = sb0[c2], a1 = sb0[c2 + 1];
#pragma unroll
    for (int i = 0; i < HID; ++i) {
        const float hb = sh[0][w][i];
        const float2 wv = *reinterpret_cast<const float2*>(&sW[i * HID + c2]);
        a0 = fmaf(hb, wv.x, a0);
        a1 = fmaf(hb, wv.y, a1);
    }
    __syncthreads();   // all warps done reading sW(W0)
    sh[1][w][c2]     = fmaxf(a0, 0.0f);
    sh[1][w][c2 + 1] = fmaxf(a1, 0.0f);

    // ---- stage W1 ----
#pragma unroll
    for (int i = t; i < HID * HID / 4; i += 256)
        reinterpret_cast<float4*>(sW)[i] = reinterpret_cast<const float4*>(W1)[i];
    __syncthreads();

    // ---- layer 1 ----
    a0 = sb1[c2]; a1 = sb1[c2 + 1];
#pragma unroll
    for (int i = 0; i < HID; ++i) {
        const float hb = sh[1][w][i];
        const float2 wv = *reinterpret_cast<const float2*>(&sW[i * HID + c2]);
        a0 = fmaf(hb, wv.x, a0);
        a1 = fmaf(hb, wv.y, a1);
    }
    __syncthreads();   // all warps done reading sW(W1) -> s_o reusable later
    sh[0][w][c2]     = fmaxf(a0, 0.0f);
    sh[0][w][c2 + 1] = fmaxf(a1, 0.0f);
    __syncthreads();   // head reads rows cross-warp

    // ---- head + sigmoid: 32 threads cover 8 rows x 4 units ----
    if (t < 32) {
        const int hr = t >> 2;
        const int jo = t & 3;
        float a2 = sbo[jo];
#pragma unroll
        for (int i = 0; i < HID; ++i) a2 = fmaf(sh[0][hr][i], sWo[i * 4 + jo], a2);
        float pv = 1.0f / (1.0f + expf(-a2));
        sp[hr][jo] = fminf(fmaxf(pv, EPSF), 1.0f - EPSF);
    }
    __syncthreads();

    // ---- odds-space constants per row ----
    if (t < BWARPS) {
        const float l  = sp[t][0];
        const float gg = sp[t][1];
        const float s  = sp[t][2];
        const float pr = sp[t][3];
        const float il = 1.0f / (1.0f - l);
        cA1[t] = (1.0f - s) / (gg * (1.0f - l));
        cA0[t] = s / ((1.0f - gg) * (1.0f - l));
        cB[t]  = l * il;
        cO0[t] = pr / (1.0f - pr);
        cS1[t] = 1.0f - s;
        cGG[t] = gg;
    }
    __syncthreads();

    // =================== scan phase (R10 body) ===================
    const float A0 = cA0[w];
    const float A1 = cA1[w];
    const float Bc = cB[w];
    const float s1 = cS1[w];
    const float gg = cGG[w];
    const float o0 = cO0[w];
    const float OMAX = (1.0f - EPSF) / EPSF;

    // compose segment map f(o) = min(a*o + b, c)
    float a = 1.0f, b = 0.0f, cc = OMAX;
#pragma unroll
    for (int j = 0; j < SLEN; ++j) {
        const float A = ((mask >> j) & 1u) ? A1 : A0;
        cc = fminf(fmaf(A, cc, Bc), OMAX);
        b  = fmaf(A, b, Bc);
        a  = A * a;
    }

    // inclusive Kogge-Stone scan over maps
#pragma unroll
    for (int d = 1; d < 32; d <<= 1) {
        const float ap = __shfl_up_sync(0xffffffffu, a,  d);
        const float bp = __shfl_up_sync(0xffffffffu, b,  d);
        const float cp = __shfl_up_sync(0xffffffffu, cc, d);
        if (lane >= d) {
            const float bn = fmaf(a, bp, b);
            const float cn = fminf(fmaf(a, cp, b), cc);
            a  = a * ap;
            b  = bn;
            cc = cn;
        }
    }
    const float ap = __shfl_up_sync(0xffffffffu, a,  1);
    const float bp = __shfl_up_sync(0xffffffffu, b,  1);
    const float cp = __shfl_up_sync(0xffffffffu, cc, 1);
    float o = (lane == 0) ? o0 : fminf(fmaf(ap, o0, bp), cp);

    // emit: batch 4 steps into float4, STS.128
    float* const so = &s_o[w][lane * OPITCH];
#pragma unroll
    for (int j4 = 0; j4 < SLEN / 4; ++j4) {
        float4 ov;
        {   const float A = ((mask >> (4*j4+0)) & 1u) ? A1 : A0;
            ov.x = o;  o = fminf(fmaf(A, o, Bc), OMAX); }
        {   const float A = ((mask >> (4*j4+1)) & 1u) ? A1 : A0;
            ov.y = o;  o = fminf(fmaf(A, o, Bc), OMAX); }
        {   const float A = ((mask >> (4*j4+2)) & 1u) ? A1 : A0;
            ov.z = o;  o = fminf(fmaf(A, o, Bc), OMAX); }
        {   const float A = ((mask >> (4*j4+3)) & 1u) ? A1 : A0;
            ov.w = o;  o = fminf(fmaf(A, o, Bc), OMAX); }
        *reinterpret_cast<float4*>(so + 4 * j4) = ov;
    }
    __syncwarp();

    // drain: LDS.128 + rcp x4 + 2x STG.128 per group
    float* const outc = out + (size_t)row * T_LEN;
    float* const outl = out + (size_t)NUM_B * T_LEN + (size_t)row * T_LEN;
    const int sgl = lane >> 3;
    const int k4  = (lane & 7) * 4;
#pragma unroll
    for (int dd = 0; dd < 8; ++dd) {
        const int seg = dd * 4 + sgl;
        const float4 ov = *reinterpret_cast<const float4*>(&s_o[w][seg * OPITCH + k4]);
        float4 lv, cv;
        float inv;
        asm("rcp.approx.ftz.f32 %0, %1;" : "=f"(inv) : "f"(1.0f + ov.x));
        lv.x = ov.x * inv;  cv.x = fmaf(ov.x, s1, gg) * inv;
        asm("rcp.approx.ftz.f32 %0, %1;" : "=f"(inv) : "f"(1.0f + ov.y));
        lv.y = ov.y * inv;  cv.y = fmaf(ov.y, s1, gg) * inv;
        asm("rcp.approx.ftz.f32 %0, %1;" : "=f"(inv) : "f"(1.0f + ov.z));
        lv.z = ov.z * inv;  cv.z = fmaf(ov.z, s1, gg) * inv;
        asm("rcp.approx.ftz.f32 %0, %1;" : "=f"(inv) : "f"(1.0f + ov.w));
        lv.w = ov.w * inv;  cv.w = fmaf(ov.w, s1, gg) * inv;
        *reinterpret_cast<float4*>(outc + seg * SLEN + k4) = cv;
        *reinterpret_cast<float4*>(outl + seg * SLEN + k4) = lv;
    }
}

// ---------------------------------------------------------------------------
extern "C" void kernel_launch(void* const* d_in, const int* in_sizes, int n_in,
                              void* d_out, int out_size)
{
    const int*   X     = (const int*)  d_in[0];
    const int*   y     = (const int*)  d_in[1];
    const float* embed = (const float*)d_in[2];
    const float* W0    = (const float*)d_in[3];
    const float* b0    = (const float*)d_in[4];
    const float* W1    = (const float*)d_in[5];
    const float* b1    = (const float*)d_in[6];
    const float* Wout  = (const float*)d_in[7];
    const float* bout  = (const float*)d_in[8];

    fused_kernel<<<NUM_B / BWARPS, 32 * BWARPS>>>(
        X, y, embed, W0, b0, W1, b1, Wout, bout, (float*)d_out);
}